// round 1
// baseline (speedup 1.0000x reference)
#include <cuda_runtime.h>

// Problem constants
#define BB      4
#define NN      2048
#define DIMC    1024
#define NHEADS  16
#define DHEAD   64
#define INNER   1024          // NHEADS * DHEAD
#define OUT3    3072          // 3 * INNER
#define MROWS   (BB * NN)     // 8192

// Scratch for QKV projection output: [B*N, 3*INNER] fp32 (~96 MiB, static)
__device__ float g_qkv[(size_t)MROWS * OUT3];

// ---------------------------------------------------------------------------
// Kernel 1: QKV GEMM  C[8192,3072] = X[8192,1024] @ W[1024,3072]
// 128x128 block tile, BK=8, 8x8 per thread (split 4+4 fragments, conflict-free)
// ---------------------------------------------------------------------------
__global__ __launch_bounds__(256) void qkv_gemm(const float* __restrict__ A,
                                                const float* __restrict__ W) {
    const int K = DIMC, Nc = OUT3;
    __shared__ float As[8][128];
    __shared__ float Bs[8][128];

    const int tid = threadIdx.x;
    const int bx = blockIdx.x;            // col block (0..23)
    const int by = blockIdx.y;            // row block (0..63)
    const int ty = tid >> 4;              // 0..15
    const int tx = tid & 15;              // 0..15

    // global load assignments (1 float4 each per k-tile)
    const int arow = tid >> 1;            // 0..127
    const int acol = (tid & 1) * 4;       // 0 or 4
    const int brow = tid >> 5;            // 0..7
    const int bcol = (tid & 31) * 4;      // 0..124

    const float* Ap = A + (size_t)(by * 128 + arow) * K + acol;
    const float* Bp = W + (size_t)brow * Nc + bx * 128 + bcol;

    float acc[8][8];
#pragma unroll
    for (int i = 0; i < 8; i++)
#pragma unroll
        for (int j = 0; j < 8; j++) acc[i][j] = 0.f;

    for (int k0 = 0; k0 < K; k0 += 8) {
        float4 av = *(const float4*)Ap;
        float4 bv = *(const float4*)Bp;
        As[acol + 0][arow] = av.x;
        As[acol + 1][arow] = av.y;
        As[acol + 2][arow] = av.z;
        As[acol + 3][arow] = av.w;
        *(float4*)&Bs[brow][bcol] = bv;
        __syncthreads();

#pragma unroll
        for (int k = 0; k < 8; k++) {
            float4 a0 = *(const float4*)&As[k][ty * 4];
            float4 a1 = *(const float4*)&As[k][64 + ty * 4];
            float4 b0 = *(const float4*)&Bs[k][tx * 4];
            float4 b1 = *(const float4*)&Bs[k][64 + tx * 4];
            float ra[8] = {a0.x, a0.y, a0.z, a0.w, a1.x, a1.y, a1.z, a1.w};
            float rb[8] = {b0.x, b0.y, b0.z, b0.w, b1.x, b1.y, b1.z, b1.w};
#pragma unroll
            for (int i = 0; i < 8; i++)
#pragma unroll
                for (int j = 0; j < 8; j++) acc[i][j] += ra[i] * rb[j];
        }
        __syncthreads();
        Ap += 8;
        Bp += 8 * (size_t)Nc;
    }

#pragma unroll
    for (int i = 0; i < 8; i++) {
        int row = by * 128 + ((i < 4) ? (ty * 4 + i) : (64 + ty * 4 + i - 4));
        float* Cp = g_qkv + (size_t)row * Nc + bx * 128;
        *(float4*)&Cp[tx * 4]      = make_float4(acc[i][0], acc[i][1], acc[i][2], acc[i][3]);
        *(float4*)&Cp[64 + tx * 4] = make_float4(acc[i][4], acc[i][5], acc[i][6], acc[i][7]);
    }
}

// ---------------------------------------------------------------------------
// Kernel 2: flash attention, fp32. One thread = one query row.
// Block = 128 threads = 128 queries of one (b,h). K/V staged in 64x64 smem
// tiles; online softmax with lazy max-rescale.
// ---------------------------------------------------------------------------
__global__ __launch_bounds__(128, 2) void flash_attn(float* __restrict__ out) {
    const int b = blockIdx.x >> 4;       // / NHEADS
    const int h = blockIdx.x & 15;
    const int t = threadIdx.x;
    const int qi = blockIdx.y * 128 + t;

    const float scale = 0.125f;          // 1/sqrt(64)

    float q[DHEAD], o[DHEAD];
    {
        const float* qrow = g_qkv + (size_t)(b * NN + qi) * OUT3 + h * DHEAD;
#pragma unroll
        for (int d = 0; d < DHEAD; d += 4) {
            float4 v4 = *(const float4*)(qrow + d);
            q[d + 0] = v4.x * scale;
            q[d + 1] = v4.y * scale;
            q[d + 2] = v4.z * scale;
            q[d + 3] = v4.w * scale;
        }
    }
#pragma unroll
    for (int d = 0; d < DHEAD; d++) o[d] = 0.f;
    float m = -1e30f, l = 0.f;

    __shared__ float Ks[64][DHEAD];
    __shared__ float Vs[64][DHEAD];

    const size_t kbase = (size_t)(b * NN) * OUT3 + INNER + h * DHEAD;     // K cols start at 1024
    const size_t vbase = kbase + INNER;                                   // V cols start at 2048

    for (int k0 = 0; k0 < NN; k0 += 64) {
        __syncthreads();
        // cooperative tile load: 64 rows x 16 float4 = 1024 float4; 8 per thread
#pragma unroll
        for (int it = 0; it < 8; it++) {
            int idx = t + it * 128;
            int j   = idx >> 4;
            int d4  = (idx & 15) * 4;
            size_t roff = (size_t)(k0 + j) * OUT3 + d4;
            *(float4*)&Ks[j][d4] = *(const float4*)(g_qkv + kbase + roff);
            *(float4*)&Vs[j][d4] = *(const float4*)(g_qkv + vbase + roff);
        }
        __syncthreads();

#pragma unroll 2
        for (int j = 0; j < 64; j++) {
            float s0 = 0.f, s1 = 0.f, s2 = 0.f, s3 = 0.f;
#pragma unroll
            for (int d = 0; d < DHEAD; d += 4) {
                float4 kv = *(const float4*)&Ks[j][d];
                s0 += q[d + 0] * kv.x;
                s1 += q[d + 1] * kv.y;
                s2 += q[d + 2] * kv.z;
                s3 += q[d + 3] * kv.w;
            }
            float s = (s0 + s1) + (s2 + s3);

            if (s <= m) {
                float p = __expf(s - m);
                l += p;
#pragma unroll
                for (int d = 0; d < DHEAD; d += 4) {
                    float4 vv = *(const float4*)&Vs[j][d];
                    o[d + 0] += p * vv.x;
                    o[d + 1] += p * vv.y;
                    o[d + 2] += p * vv.z;
                    o[d + 3] += p * vv.w;
                }
            } else {
                float alpha = __expf(m - s);   // rare path (~log N per thread)
                m = s;
                l = l * alpha + 1.f;
#pragma unroll
                for (int d = 0; d < DHEAD; d += 4) {
                    float4 vv = *(const float4*)&Vs[j][d];
                    o[d + 0] = o[d + 0] * alpha + vv.x;
                    o[d + 1] = o[d + 1] * alpha + vv.y;
                    o[d + 2] = o[d + 2] * alpha + vv.z;
                    o[d + 3] = o[d + 3] * alpha + vv.w;
                }
            }
        }
    }

    const float inv = 1.f / l;
    float* orow = out + (size_t)(b * NN + qi) * INNER + h * DHEAD;
#pragma unroll
    for (int d = 0; d < DHEAD; d += 4) {
        *(float4*)(orow + d) =
            make_float4(o[d] * inv, o[d + 1] * inv, o[d + 2] * inv, o[d + 3] * inv);
    }
}

// ---------------------------------------------------------------------------
extern "C" void kernel_launch(void* const* d_in, const int* in_sizes, int n_in,
                              void* d_out, int out_size) {
    const float* x = (const float*)d_in[0];       // [B, N, DIM]
    const float* w = (const float*)d_in[1];       // [DIM, 3*INNER]
    float* out = (float*)d_out;                   // [B, N, INNER]

    dim3 g1(OUT3 / 128, MROWS / 128);             // (24, 64)
    qkv_gemm<<<g1, 256>>>(x, w);

    dim3 g2(BB * NHEADS, NN / 128);               // (64, 16)
    flash_attn<<<g2, 128>>>(out);
}

// round 4
// speedup vs baseline: 3.5348x; 3.5348x over previous
#include <cuda_runtime.h>
#include <cuda_bf16.h>
#include <cstdint>

#define BB      4
#define NN      2048
#define DIMC    1024
#define NHEADS  16
#define DHEAD   64
#define INNER   1024
#define OUT3    3072
#define MROWS   8192

// bf16 hi/lo copies of inputs and of the QKV projection output
__device__ __nv_bfloat16 g_xh[(size_t)MROWS * DIMC];
__device__ __nv_bfloat16 g_xl[(size_t)MROWS * DIMC];
__device__ __nv_bfloat16 g_wh[(size_t)DIMC * OUT3];
__device__ __nv_bfloat16 g_wl[(size_t)DIMC * OUT3];
__device__ __nv_bfloat16 g_ch[(size_t)MROWS * OUT3];
__device__ __nv_bfloat16 g_cl[(size_t)MROWS * OUT3];

// ---------------------------------------------------------------------------
// helpers
// ---------------------------------------------------------------------------
__device__ __forceinline__ uint32_t smem_u32(const void* p) {
    uint32_t a;
    asm("{ .reg .u64 t; cvta.to.shared.u64 t, %1; cvt.u32.u64 %0, t; }" : "=r"(a) : "l"(p));
    return a;
}

#define CP16(dst, src) \
    asm volatile("cp.async.cg.shared.global [%0], [%1], 16;" :: "r"(dst), \
        "l"((unsigned long long)__cvta_generic_to_global(src)))
#define CP_COMMIT() asm volatile("cp.async.commit_group;")
#define CP_WAIT0()  asm volatile("cp.async.wait_group 0;")
#define CP_WAIT1()  asm volatile("cp.async.wait_group 1;")

#define LDSM4(R, addr) asm volatile( \
    "ldmatrix.sync.aligned.m8n8.x4.shared.b16 {%0,%1,%2,%3}, [%4];" \
    : "=r"((R)[0]), "=r"((R)[1]), "=r"((R)[2]), "=r"((R)[3]) : "r"(addr))
#define LDSM4T(R, addr) asm volatile( \
    "ldmatrix.sync.aligned.m8n8.x4.trans.shared.b16 {%0,%1,%2,%3}, [%4];" \
    : "=r"((R)[0]), "=r"((R)[1]), "=r"((R)[2]), "=r"((R)[3]) : "r"(addr))

#define MMA(D, A, B0, B1) asm volatile( \
    "mma.sync.aligned.m16n8k16.row.col.f32.bf16.bf16.f32 " \
    "{%0,%1,%2,%3}, {%4,%5,%6,%7}, {%8,%9}, {%0,%1,%2,%3};" \
    : "+f"((D)[0]), "+f"((D)[1]), "+f"((D)[2]), "+f"((D)[3]) \
    : "r"((A)[0]), "r"((A)[1]), "r"((A)[2]), "r"((A)[3]), "r"(B0), "r"(B1))

// split two fp32 into packed bf16 hi and lo words
__device__ __forceinline__ void split2(float a, float b, uint32_t& h, uint32_t& l) {
    __nv_bfloat16 ha = __float2bfloat16_rn(a), hb = __float2bfloat16_rn(b);
    __nv_bfloat16 la = __float2bfloat16_rn(a - __bfloat162float(ha));
    __nv_bfloat16 lb = __float2bfloat16_rn(b - __bfloat162float(hb));
    h = (uint32_t)__bfloat16_as_ushort(ha) | ((uint32_t)__bfloat16_as_ushort(hb) << 16);
    l = (uint32_t)__bfloat16_as_ushort(la) | ((uint32_t)__bfloat16_as_ushort(lb) << 16);
}

// ---------------------------------------------------------------------------
// prep: fp32 -> bf16 hi/lo
// ---------------------------------------------------------------------------
__global__ void split_kernel(const float* __restrict__ src,
                             __nv_bfloat16* __restrict__ h,
                             __nv_bfloat16* __restrict__ l, int n4) {
    int i = blockIdx.x * blockDim.x + threadIdx.x;
    if (i >= n4) return;
    float4 v = ((const float4*)src)[i];
    uint32_t h0, l0, h1, l1;
    split2(v.x, v.y, h0, l0);
    split2(v.z, v.w, h1, l1);
    ((uint2*)h)[i] = make_uint2(h0, h1);
    ((uint2*)l)[i] = make_uint2(l0, l1);
}

// ---------------------------------------------------------------------------
// QKV GEMM: C[8192,3072] = X @ W, bf16 split 3-product, mma.sync
// CTA 128x256, BK=32, 8 warps (warp tile 64x64), 2-stage cp.async pipeline
// ---------------------------------------------------------------------------
#define G_STAGE 54272            // Ah(10240)+Al(10240)+Bh(16896)+Bl(16896)
#define G_SMEM  (2 * G_STAGE)

__global__ __launch_bounds__(256, 1) void qkv_gemm_mma(const float* dummy) {
    extern __shared__ char smc[];
    const uint32_t sb = smem_u32(smc);
    const int tid = threadIdx.x;
    const int w = tid >> 5, L = tid & 31;
    const int wm = w >> 2, wn = w & 3;
    const int g = L >> 2, t2 = (L & 3) * 2;
    const int bm = blockIdx.y * 128;
    const int bn = blockIdx.x * 256;

    float acc[4][8][4];
#pragma unroll
    for (int i = 0; i < 4; i++)
#pragma unroll
        for (int j = 0; j < 8; j++)
#pragma unroll
            for (int e = 0; e < 4; e++) acc[i][j][e] = 0.f;

    // ---- stage loader
    auto load_stage = [&](int kt, int s) {
        const uint32_t st = sb + s * G_STAGE;
        const int k0 = kt * 32;
#pragma unroll
        for (int i = 0; i < 2; i++) {               // A: 128x32, both h/l
            int idx = tid + 256 * i;
            int r = idx >> 2, c = idx & 3;
            size_t go = (size_t)(bm + r) * DIMC + k0 + c * 8;
            uint32_t d = st + r * 80 + c * 16;
            CP16(d, g_xh + go);
            CP16(d + 10240, g_xl + go);
        }
#pragma unroll
        for (int i = 0; i < 4; i++) {               // B: 32x256, both h/l
            int idx = tid + 256 * i;
            int r = idx >> 5, c = idx & 31;
            size_t go = (size_t)(k0 + r) * OUT3 + bn + c * 8;
            uint32_t d = st + 20480 + r * 528 + c * 16;
            CP16(d, g_wh + go);
            CP16(d + 16896, g_wl + go);
        }
    };

    auto mma_stage = [&](int s) {
        const uint32_t st = sb + s * G_STAGE;
        const uint32_t rsel = (L & 15), hsel = (L >> 4) * 16;
#pragma unroll
        for (int n16 = 0; n16 < 4; n16++) {
            uint32_t bh[2][4], bl[2][4];
#pragma unroll
            for (int ks = 0; ks < 2; ks++) {
                uint32_t ba = st + 20480 + (ks * 16 + rsel) * 528 +
                              (wn * 64 + n16 * 16) * 2 + hsel;
                LDSM4T(bh[ks], ba);
                LDSM4T(bl[ks], ba + 16896);
            }
#pragma unroll
            for (int mf = 0; mf < 4; mf++) {
#pragma unroll
                for (int ks = 0; ks < 2; ks++) {
                    uint32_t aa = st + (wm * 64 + mf * 16 + rsel) * 80 + ks * 32 + hsel;
                    uint32_t ah[4], al[4];
                    LDSM4(ah, aa);
                    LDSM4(al, aa + 10240);
                    float* d0 = acc[mf][2 * n16];
                    float* d1 = acc[mf][2 * n16 + 1];
                    MMA(d0, ah, bh[ks][0], bh[ks][1]);
                    MMA(d0, ah, bl[ks][0], bl[ks][1]);
                    MMA(d0, al, bh[ks][0], bh[ks][1]);
                    MMA(d1, ah, bh[ks][2], bh[ks][3]);
                    MMA(d1, ah, bl[ks][2], bl[ks][3]);
                    MMA(d1, al, bh[ks][2], bh[ks][3]);
                }
            }
        }
    };

    load_stage(0, 0);
    CP_COMMIT();
    for (int kt = 0; kt < 32; kt++) {
        if (kt < 31) {
            load_stage(kt + 1, (kt + 1) & 1);
            CP_COMMIT();
            CP_WAIT1();
        } else {
            CP_WAIT0();
        }
        __syncthreads();
        mma_stage(kt & 1);
        __syncthreads();
    }

    // epilogue: scaled (Q region) hi/lo bf16 store
#pragma unroll
    for (int mf = 0; mf < 4; mf++) {
        int r0 = bm + wm * 64 + mf * 16 + g;
#pragma unroll
        for (int nf = 0; nf < 8; nf++) {
            int c = bn + wn * 64 + nf * 8 + t2;
            float sc = (c < INNER) ? 0.125f : 1.0f;
            uint32_t h, l;
            split2(acc[mf][nf][0] * sc, acc[mf][nf][1] * sc, h, l);
            *(uint32_t*)(g_ch + (size_t)r0 * OUT3 + c) = h;
            *(uint32_t*)(g_cl + (size_t)r0 * OUT3 + c) = l;
            split2(acc[mf][nf][2] * sc, acc[mf][nf][3] * sc, h, l);
            *(uint32_t*)(g_ch + (size_t)(r0 + 8) * OUT3 + c) = h;
            *(uint32_t*)(g_cl + (size_t)(r0 + 8) * OUT3 + c) = l;
        }
    }
}

// ---------------------------------------------------------------------------
// Flash attention, mma.sync, bf16 split. CTA = (b,h) x 128 q rows, 8 warps.
// ---------------------------------------------------------------------------
#define A_QH    0
#define A_QL    18432
#define A_ST0   36864
#define A_STAGE 36864            // Kh(9216)+Kl+Vh+Vl
#define A_SMEM  (A_ST0 + 2 * A_STAGE)

__global__ __launch_bounds__(256, 1) void flash_attn_mma(float* __restrict__ out) {
    extern __shared__ char smc[];
    const uint32_t sb = smem_u32(smc);
    const int tid = threadIdx.x;
    const int w = tid >> 5, L = tid & 31;
    const int g = L >> 2, t2 = (L & 3) * 2;
    const int b = blockIdx.x >> 4, h = blockIdx.x & 15;
    const int qrow0 = b * NN + blockIdx.y * 128;

    // ---- Q tile load (hi/lo) into smem
#pragma unroll
    for (int i = 0; i < 8; i++) {
        int idx = tid + 256 * i;           // 0..2047
        int arr = idx >> 10;               // 0: hi, 1: lo
        int rem = idx & 1023;
        int r = rem >> 3, c = rem & 7;
        size_t go = (size_t)(qrow0 + r) * OUT3 + h * DHEAD + c * 8;
        uint32_t d = sb + arr * 18432 + r * 144 + c * 16;
        CP16(d, (arr ? g_cl : g_ch) + go);
    }

    auto load_kv = [&](int t, int s) {
        const uint32_t st = sb + A_ST0 + s * A_STAGE;
#pragma unroll
        for (int i = 0; i < 8; i++) {
            int idx = tid + 256 * i;       // 0..2047
            int arr = idx >> 9;            // 0:Kh 1:Kl 2:Vh 3:Vl
            int rem = idx & 511;
            int r = rem >> 3, c = rem & 7;
            size_t go = (size_t)(b * NN + t * 64 + r) * OUT3 + h * DHEAD + c * 8;
            const __nv_bfloat16* src =
                (arr == 0) ? g_ch + INNER + go :
                (arr == 1) ? g_cl + INNER + go :
                (arr == 2) ? g_ch + 2 * INNER + go :
                             g_cl + 2 * INNER + go;
            CP16(st + arr * 9216 + r * 144 + c * 16, src);
        }
    };

    load_kv(0, 0);
    CP_COMMIT();

    uint32_t qh[4][4], ql[4][4];
    float o[8][4];
#pragma unroll
    for (int i = 0; i < 8; i++)
#pragma unroll
        for (int e = 0; e < 4; e++) o[i][e] = 0.f;
    float m0 = -1e30f, m1 = -1e30f, l0 = 0.f, l1 = 0.f;

    const uint32_t rsel = (L & 15), hsel = (L >> 4) * 16;

    for (int t = 0; t < NN / 64; t++) {
        if (t < NN / 64 - 1) {
            load_kv(t + 1, (t + 1) & 1);
            CP_COMMIT();
            CP_WAIT1();
        } else {
            CP_WAIT0();
        }
        __syncthreads();

        if (t == 0) {
#pragma unroll
            for (int ks = 0; ks < 4; ks++) {
                uint32_t qa = sb + (w * 16 + rsel) * 144 + ks * 32 + hsel;
                LDSM4(qh[ks], qa);
                LDSM4(ql[ks], qa + 18432);
            }
        }

        const uint32_t st = sb + A_ST0 + (t & 1) * A_STAGE;

        // ---- S = Qs @ K^T  (3 products)
        float s[8][4];
#pragma unroll
        for (int i = 0; i < 8; i++)
#pragma unroll
            for (int e = 0; e < 4; e++) s[i][e] = 0.f;
#pragma unroll
        for (int n16 = 0; n16 < 4; n16++) {
#pragma unroll
            for (int ks = 0; ks < 4; ks++) {
                uint32_t ka = st + (n16 * 16 + rsel) * 144 + ks * 32 + hsel;
                uint32_t kh[4], kl[4];
                LDSM4(kh, ka);
                LDSM4(kl, ka + 9216);
                float* d0 = s[2 * n16];
                float* d1 = s[2 * n16 + 1];
                MMA(d0, qh[ks], kh[0], kh[2]);   // non-trans: nfrag0 = {r0,r2}
                MMA(d0, qh[ks], kl[0], kl[2]);
                MMA(d0, ql[ks], kh[0], kh[2]);
                MMA(d1, qh[ks], kh[1], kh[3]);
                MMA(d1, qh[ks], kl[1], kl[3]);
                MMA(d1, ql[ks], kh[1], kh[3]);
            }
        }

        // ---- online softmax
        float mx0 = -1e30f, mx1 = -1e30f;
#pragma unroll
        for (int i = 0; i < 8; i++) {
            mx0 = fmaxf(mx0, fmaxf(s[i][0], s[i][1]));
            mx1 = fmaxf(mx1, fmaxf(s[i][2], s[i][3]));
        }
        mx0 = fmaxf(mx0, __shfl_xor_sync(0xffffffffu, mx0, 1));
        mx0 = fmaxf(mx0, __shfl_xor_sync(0xffffffffu, mx0, 2));
        mx1 = fmaxf(mx1, __shfl_xor_sync(0xffffffffu, mx1, 1));
        mx1 = fmaxf(mx1, __shfl_xor_sync(0xffffffffu, mx1, 2));
        float mn0 = fmaxf(m0, mx0), mn1 = fmaxf(m1, mx1);
        float al0 = __expf(m0 - mn0), al1 = __expf(m1 - mn1);
        m0 = mn0; m1 = mn1;
        l0 *= al0; l1 *= al1;
#pragma unroll
        for (int i = 0; i < 8; i++) {
            o[i][0] *= al0; o[i][1] *= al0;
            o[i][2] *= al1; o[i][3] *= al1;
        }

        uint32_t aph[4][4], apl[4][4];
#pragma unroll
        for (int nf = 0; nf < 8; nf++) {
            float p0 = __expf(s[nf][0] - mn0);
            float p1 = __expf(s[nf][1] - mn0);
            float p2 = __expf(s[nf][2] - mn1);
            float p3 = __expf(s[nf][3] - mn1);
            l0 += p0 + p1;
            l1 += p2 + p3;
            int kk = nf >> 1, pos = nf & 1;
            split2(p0, p1, aph[kk][pos * 2 + 0], apl[kk][pos * 2 + 0]);
            split2(p2, p3, aph[kk][pos * 2 + 1], apl[kk][pos * 2 + 1]);
        }

        // ---- O += P @ V  (3 products)
#pragma unroll
        for (int d16 = 0; d16 < 4; d16++) {
#pragma unroll
            for (int kk = 0; kk < 4; kk++) {
                uint32_t va = st + 18432 + (kk * 16 + rsel) * 144 + d16 * 32 + hsel;
                uint32_t vh[4], vl[4];
                LDSM4T(vh, va);
                LDSM4T(vl, va + 9216);
                float* d0 = o[2 * d16];
                float* d1 = o[2 * d16 + 1];
                MMA(d0, aph[kk], vh[0], vh[1]);  // trans: nfrag0 = {r0,r1}
                MMA(d0, aph[kk], vl[0], vl[1]);
                MMA(d0, apl[kk], vh[0], vh[1]);
                MMA(d1, aph[kk], vh[2], vh[3]);
                MMA(d1, aph[kk], vl[2], vl[3]);
                MMA(d1, apl[kk], vh[2], vh[3]);
            }
        }
        __syncthreads();
    }

    // ---- epilogue
    l0 += __shfl_xor_sync(0xffffffffu, l0, 1);
    l0 += __shfl_xor_sync(0xffffffffu, l0, 2);
    l1 += __shfl_xor_sync(0xffffffffu, l1, 1);
    l1 += __shfl_xor_sync(0xffffffffu, l1, 2);
    float inv0 = 1.f / l0, inv1 = 1.f / l1;
    int row0 = qrow0 + w * 16 + g;
#pragma unroll
    for (int nf = 0; nf < 8; nf++) {
        int c = h * DHEAD + nf * 8 + t2;
        *(float2*)(out + (size_t)row0 * INNER + c) =
            make_float2(o[nf][0] * inv0, o[nf][1] * inv0);
        *(float2*)(out + (size_t)(row0 + 8) * INNER + c) =
            make_float2(o[nf][2] * inv1, o[nf][3] * inv1);
    }
}

// ---------------------------------------------------------------------------
extern "C" void kernel_launch(void* const* d_in, const int* in_sizes, int n_in,
                              void* d_out, int out_size) {
    const float* x = (const float*)d_in[0];
    const float* w = (const float*)d_in[1];
    float* out = (float*)d_out;

    cudaFuncSetAttribute(qkv_gemm_mma, cudaFuncAttributeMaxDynamicSharedMemorySize, G_SMEM);
    cudaFuncSetAttribute(flash_attn_mma, cudaFuncAttributeMaxDynamicSharedMemorySize, A_SMEM);

    // resolve device-global addresses (host side, no alloc)
    __nv_bfloat16 *xh, *xl, *wh, *wl;
    cudaGetSymbolAddress((void**)&xh, g_xh);
    cudaGetSymbolAddress((void**)&xl, g_xl);
    cudaGetSymbolAddress((void**)&wh, g_wh);
    cudaGetSymbolAddress((void**)&wl, g_wl);

    split_kernel<<<(MROWS * DIMC / 4 + 255) / 256, 256>>>(x, xh, xl, MROWS * DIMC / 4);
    split_kernel<<<(DIMC * OUT3 / 4 + 255) / 256, 256>>>(w, wh, wl, DIMC * OUT3 / 4);

    dim3 g1(OUT3 / 256, MROWS / 128);   // (12, 64)
    qkv_gemm_mma<<<g1, 256, G_SMEM>>>(x);

    dim3 g2(BB * NHEADS, NN / 128);     // (64, 16)
    flash_attn_mma<<<g2, 256, A_SMEM>>>(out);
}

// round 6
// speedup vs baseline: 4.5965x; 1.3004x over previous
#include <cuda_runtime.h>
#include <cuda_fp16.h>
#include <cstdint>

#define BB      4
#define NN      2048
#define DIMC    1024
#define NHEADS  16
#define DHEAD   64
#define INNER   1024
#define OUT3    3072
#define MROWS   8192

// fp16 hi/lo copies of inputs; fp16 hi/lo of QKV output (lo only used for Q)
__device__ __half g_x16h[(size_t)MROWS * DIMC];
__device__ __half g_x16l[(size_t)MROWS * DIMC];
__device__ __half g_w16h[(size_t)DIMC * OUT3];
__device__ __half g_w16l[(size_t)DIMC * OUT3];
__device__ __half g_c16h[(size_t)MROWS * OUT3];
__device__ __half g_c16l[(size_t)MROWS * OUT3];

// ---------------------------------------------------------------------------
// helpers
// ---------------------------------------------------------------------------
__device__ __forceinline__ uint32_t smem_u32(const void* p) {
    uint32_t a;
    asm("{ .reg .u64 t; cvta.to.shared.u64 t, %1; cvt.u32.u64 %0, t; }" : "=r"(a) : "l"(p));
    return a;
}

#define CP16(dst, src) \
    asm volatile("cp.async.cg.shared.global [%0], [%1], 16;" :: "r"(dst), \
        "l"((unsigned long long)__cvta_generic_to_global(src)))
#define CP_COMMIT() asm volatile("cp.async.commit_group;")
#define CP_WAIT0()  asm volatile("cp.async.wait_group 0;")

#define LDSM4(R, addr) asm volatile( \
    "ldmatrix.sync.aligned.m8n8.x4.shared.b16 {%0,%1,%2,%3}, [%4];" \
    : "=r"((R)[0]), "=r"((R)[1]), "=r"((R)[2]), "=r"((R)[3]) : "r"(addr))
#define LDSM4T(R, addr) asm volatile( \
    "ldmatrix.sync.aligned.m8n8.x4.trans.shared.b16 {%0,%1,%2,%3}, [%4];" \
    : "=r"((R)[0]), "=r"((R)[1]), "=r"((R)[2]), "=r"((R)[3]) : "r"(addr))

#define MMA(D, A, B0, B1) asm volatile( \
    "mma.sync.aligned.m16n8k16.row.col.f32.f16.f16.f32 " \
    "{%0,%1,%2,%3}, {%4,%5,%6,%7}, {%8,%9}, {%0,%1,%2,%3};" \
    : "+f"((D)[0]), "+f"((D)[1]), "+f"((D)[2]), "+f"((D)[3]) \
    : "r"((A)[0]), "r"((A)[1]), "r"((A)[2]), "r"((A)[3]), "r"(B0), "r"(B1))

// split two fp32 into packed fp16 hi and lo words (lo element in low half)
__device__ __forceinline__ void split2h(float a, float b, uint32_t& h, uint32_t& l) {
    __half ha = __float2half_rn(a), hb = __float2half_rn(b);
    __half la = __float2half_rn(a - __half2float(ha));
    __half lb = __float2half_rn(b - __half2float(hb));
    h = (uint32_t)__half_as_ushort(ha) | ((uint32_t)__half_as_ushort(hb) << 16);
    l = (uint32_t)__half_as_ushort(la) | ((uint32_t)__half_as_ushort(lb) << 16);
}

// ---------------------------------------------------------------------------
// prep: fp32 -> fp16 hi/lo
// ---------------------------------------------------------------------------
__global__ void split_f16(const float* __restrict__ src,
                          __half* __restrict__ h, __half* __restrict__ l, int n4) {
    int i = blockIdx.x * blockDim.x + threadIdx.x;
    if (i >= n4) return;
    float4 v = ((const float4*)src)[i];
    uint32_t h0, l0, h1, l1;
    split2h(v.x, v.y, h0, l0);
    split2h(v.z, v.w, h1, l1);
    ((uint2*)h)[i] = make_uint2(h0, h1);
    ((uint2*)l)[i] = make_uint2(l0, l1);
}

// ---------------------------------------------------------------------------
// QKV GEMM: fp16 3-product (XhWh + XhWl + XlWh), CTA 128x256, BK=64, 8 warps
// ---------------------------------------------------------------------------
#define GA_H 0
#define GA_L 18432
#define GB_H 36864
#define GB_L 70656
#define G_STAGE 104448
#define G_SMEM  (2 * G_STAGE)   // 208896

__global__ __launch_bounds__(256, 1) void qkv_gemm_f16() {
    extern __shared__ char smc[];
    const uint32_t sb = smem_u32(smc);
    const int tid = threadIdx.x;
    const int w = tid >> 5, L = tid & 31;
    const int wm = w >> 2, wn = w & 3;
    const int g = L >> 2, t2 = (L & 3) * 2;
    const int bm = blockIdx.y * 128;
    const int bn = blockIdx.x * 256;

    float acc[4][8][4];
#pragma unroll
    for (int i = 0; i < 4; i++)
#pragma unroll
        for (int j = 0; j < 8; j++)
#pragma unroll
            for (int e = 0; e < 4; e++) acc[i][j][e] = 0.f;

    auto load_stage = [&](int kt, int s) {
        const uint32_t st = sb + s * G_STAGE;
        const int k0 = kt * 64;
#pragma unroll
        for (int i = 0; i < 4; i++) {                // A: 128x64, h and l
            int idx = tid + 256 * i;
            int r = idx >> 3, c = idx & 7;
            size_t go = (size_t)(bm + r) * DIMC + k0 + c * 8;
            uint32_t d = st + r * 144 + c * 16;
            CP16(d + GA_H, g_x16h + go);
            CP16(d + GA_L, g_x16l + go);
        }
#pragma unroll
        for (int i = 0; i < 8; i++) {                // B: 64x256, h and l
            int idx = tid + 256 * i;
            int r = idx >> 5, c = idx & 31;
            size_t go = (size_t)(k0 + r) * OUT3 + bn + c * 8;
            uint32_t d = st + r * 528 + c * 16;
            CP16(d + GB_H, g_w16h + go);
            CP16(d + GB_L, g_w16l + go);
        }
    };

    auto mma_stage = [&](int s) {
        const uint32_t st = sb + s * G_STAGE;
        const uint32_t rsel = (L & 15), hsel = (L >> 4) * 16;
#pragma unroll
        for (int ks = 0; ks < 4; ks++) {
            uint32_t ah[4][4], al[4][4];
#pragma unroll
            for (int mf = 0; mf < 4; mf++) {
                uint32_t aa = st + (wm * 64 + mf * 16 + rsel) * 144 + ks * 32 + hsel;
                LDSM4(ah[mf], aa + GA_H);
                LDSM4(al[mf], aa + GA_L);
            }
#pragma unroll
            for (int n16 = 0; n16 < 4; n16++) {
                uint32_t ba = st + GB_H + (ks * 16 + rsel) * 528 +
                              (wn * 64 + n16 * 16) * 2 + hsel;
                uint32_t bh[4], bl[4];
                LDSM4T(bh, ba);
                LDSM4T(bl, ba + (GB_L - GB_H));
#pragma unroll
                for (int mf = 0; mf < 4; mf++) {
                    float* d0 = acc[mf][2 * n16];
                    float* d1 = acc[mf][2 * n16 + 1];
                    MMA(d0, ah[mf], bh[0], bh[1]);
                    MMA(d0, ah[mf], bl[0], bl[1]);
                    MMA(d0, al[mf], bh[0], bh[1]);
                    MMA(d1, ah[mf], bh[2], bh[3]);
                    MMA(d1, ah[mf], bl[2], bl[3]);
                    MMA(d1, al[mf], bh[2], bh[3]);
                }
            }
        }
    };

    load_stage(0, 0);
    CP_COMMIT();
    for (int kt = 0; kt < 16; kt++) {
        CP_WAIT0();
        __syncthreads();
        if (kt < 15) {
            load_stage(kt + 1, (kt + 1) & 1);
            CP_COMMIT();
        }
        mma_stage(kt & 1);
    }

    // epilogue: scale Q region, store fp16 hi always, lo only for Q cols
#pragma unroll
    for (int mf = 0; mf < 4; mf++) {
        int r0 = bm + wm * 64 + mf * 16 + g;
#pragma unroll
        for (int nf = 0; nf < 8; nf++) {
            int c = bn + wn * 64 + nf * 8 + t2;
            float sc = (c < INNER) ? 0.125f : 1.0f;
            uint32_t h, l;
            split2h(acc[mf][nf][0] * sc, acc[mf][nf][1] * sc, h, l);
            *(uint32_t*)(g_c16h + (size_t)r0 * OUT3 + c) = h;
            if (c < INNER) *(uint32_t*)(g_c16l + (size_t)r0 * OUT3 + c) = l;
            split2h(acc[mf][nf][2] * sc, acc[mf][nf][3] * sc, h, l);
            *(uint32_t*)(g_c16h + (size_t)(r0 + 8) * OUT3 + c) = h;
            if (c < INNER) *(uint32_t*)(g_c16l + (size_t)(r0 + 8) * OUT3 + c) = l;
        }
    }
}

// ---------------------------------------------------------------------------
// Flash attention fp16: QK = (Qh+Ql)K, PV = (Ph+Pl)V. 64-q CTA, 4 warps.
// ---------------------------------------------------------------------------
#define F_QH    0
#define F_QL    9216
#define F_ST0   18432
#define F_V     9216            // within stage: K at 0, V at 9216
#define F_STAGE 18432
#define F_SMEM  (F_ST0 + 2 * F_STAGE)   // 55296

__global__ __launch_bounds__(128, 3) void flash_attn_f16(float* __restrict__ out) {
    extern __shared__ char smc[];
    const uint32_t sb = smem_u32(smc);
    const int tid = threadIdx.x;
    const int w = tid >> 5, L = tid & 31;
    const int g = L >> 2, t2 = (L & 3) * 2;
    const int b = blockIdx.x >> 4, h = blockIdx.x & 15;
    const int qrow0 = b * NN + blockIdx.y * 64;

    // Q tile (hi/lo): 64 rows x 8 chunks x 2 arrays = 1024 CP16
#pragma unroll
    for (int i = 0; i < 8; i++) {
        int idx = tid + 128 * i;
        int arr = idx >> 9;                 // 0: hi, 1: lo
        int rem = idx & 511;
        int r = rem >> 3, c = rem & 7;
        size_t go = (size_t)(qrow0 + r) * OUT3 + h * DHEAD + c * 8;
        CP16(sb + arr * 9216 + r * 144 + c * 16, (arr ? g_c16l : g_c16h) + go);
    }

    auto load_kv = [&](int t, int s) {
        const uint32_t st = sb + F_ST0 + s * F_STAGE;
#pragma unroll
        for (int i = 0; i < 8; i++) {
            int idx = tid + 128 * i;
            int arr = idx >> 9;             // 0: K, 1: V  (hi only)
            int rem = idx & 511;
            int r = rem >> 3, c = rem & 7;
            size_t go = (size_t)(b * NN + t * 64 + r) * OUT3 + h * DHEAD + c * 8;
            const __half* src = arr ? (g_c16h + 2 * INNER + go) : (g_c16h + INNER + go);
            CP16(st + arr * F_V + r * 144 + c * 16, src);
        }
    };

    load_kv(0, 0);
    CP_COMMIT();

    uint32_t qh[4][4], ql[4][4];
    float o[8][4];
#pragma unroll
    for (int i = 0; i < 8; i++)
#pragma unroll
        for (int e = 0; e < 4; e++) o[i][e] = 0.f;
    float m0 = -1e30f, m1 = -1e30f, l0 = 0.f, l1 = 0.f;

    const uint32_t rsel = (L & 15), hsel = (L >> 4) * 16;

    for (int t = 0; t < NN / 64; t++) {
        CP_WAIT0();
        __syncthreads();
        if (t < NN / 64 - 1) {
            load_kv(t + 1, (t + 1) & 1);
            CP_COMMIT();
        }
        if (t == 0) {
#pragma unroll
            for (int ks = 0; ks < 4; ks++) {
                uint32_t qa = sb + (w * 16 + rsel) * 144 + ks * 32 + hsel;
                LDSM4(qh[ks], qa + F_QH);
                LDSM4(ql[ks], qa + F_QL);
            }
        }

        const uint32_t st = sb + F_ST0 + (t & 1) * F_STAGE;

        // ---- S = (Qh + Ql) @ K^T
        float s[8][4];
#pragma unroll
        for (int i = 0; i < 8; i++)
#pragma unroll
            for (int e = 0; e < 4; e++) s[i][e] = 0.f;
#pragma unroll
        for (int n16 = 0; n16 < 4; n16++) {
#pragma unroll
            for (int ks = 0; ks < 4; ks++) {
                uint32_t kh[4];
                LDSM4(kh, st + (n16 * 16 + rsel) * 144 + ks * 32 + hsel);
                float* d0 = s[2 * n16];
                float* d1 = s[2 * n16 + 1];
                MMA(d0, qh[ks], kh[0], kh[2]);
                MMA(d0, ql[ks], kh[0], kh[2]);
                MMA(d1, qh[ks], kh[1], kh[3]);
                MMA(d1, ql[ks], kh[1], kh[3]);
            }
        }

        // ---- online softmax
        float mx0 = -1e30f, mx1 = -1e30f;
#pragma unroll
        for (int i = 0; i < 8; i++) {
            mx0 = fmaxf(mx0, fmaxf(s[i][0], s[i][1]));
            mx1 = fmaxf(mx1, fmaxf(s[i][2], s[i][3]));
        }
        mx0 = fmaxf(mx0, __shfl_xor_sync(0xffffffffu, mx0, 1));
        mx0 = fmaxf(mx0, __shfl_xor_sync(0xffffffffu, mx0, 2));
        mx1 = fmaxf(mx1, __shfl_xor_sync(0xffffffffu, mx1, 1));
        mx1 = fmaxf(mx1, __shfl_xor_sync(0xffffffffu, mx1, 2));
        float mn0 = fmaxf(m0, mx0), mn1 = fmaxf(m1, mx1);
        float al0 = __expf(m0 - mn0), al1 = __expf(m1 - mn1);
        m0 = mn0; m1 = mn1;
        l0 *= al0; l1 *= al1;
#pragma unroll
        for (int i = 0; i < 8; i++) {
            o[i][0] *= al0; o[i][1] *= al0;
            o[i][2] *= al1; o[i][3] *= al1;
        }

        uint32_t aph[4][4], apl[4][4];
#pragma unroll
        for (int nf = 0; nf < 8; nf++) {
            float p0 = __expf(s[nf][0] - mn0);
            float p1 = __expf(s[nf][1] - mn0);
            float p2 = __expf(s[nf][2] - mn1);
            float p3 = __expf(s[nf][3] - mn1);
            l0 += p0 + p1;
            l1 += p2 + p3;
            int kk = nf >> 1, pos = nf & 1;
            split2h(p0, p1, aph[kk][pos * 2 + 0], apl[kk][pos * 2 + 0]);
            split2h(p2, p3, aph[kk][pos * 2 + 1], apl[kk][pos * 2 + 1]);
        }

        // ---- O += (Ph + Pl) @ V
#pragma unroll
        for (int d16 = 0; d16 < 4; d16++) {
#pragma unroll
            for (int kk = 0; kk < 4; kk++) {
                uint32_t vh[4];
                LDSM4T(vh, st + F_V + (kk * 16 + rsel) * 144 + d16 * 32 + hsel);
                float* d0 = o[2 * d16];
                float* d1 = o[2 * d16 + 1];
                MMA(d0, aph[kk], vh[0], vh[1]);
                MMA(d0, apl[kk], vh[0], vh[1]);
                MMA(d1, aph[kk], vh[2], vh[3]);
                MMA(d1, apl[kk], vh[2], vh[3]);
            }
        }
    }

    // ---- epilogue
    l0 += __shfl_xor_sync(0xffffffffu, l0, 1);
    l0 += __shfl_xor_sync(0xffffffffu, l0, 2);
    l1 += __shfl_xor_sync(0xffffffffu, l1, 1);
    l1 += __shfl_xor_sync(0xffffffffu, l1, 2);
    float inv0 = 1.f / l0, inv1 = 1.f / l1;
    int row0 = qrow0 + w * 16 + g;
#pragma unroll
    for (int nf = 0; nf < 8; nf++) {
        int c = h * DHEAD + nf * 8 + t2;
        *(float2*)(out + (size_t)row0 * INNER + c) =
            make_float2(o[nf][0] * inv0, o[nf][1] * inv0);
        *(float2*)(out + (size_t)(row0 + 8) * INNER + c) =
            make_float2(o[nf][2] * inv1, o[nf][3] * inv1);
    }
}

// ---------------------------------------------------------------------------
extern "C" void kernel_launch(void* const* d_in, const int* in_sizes, int n_in,
                              void* d_out, int out_size) {
    const float* x = (const float*)d_in[0];
    const float* w = (const float*)d_in[1];
    float* out = (float*)d_out;

    cudaFuncSetAttribute(qkv_gemm_f16, cudaFuncAttributeMaxDynamicSharedMemorySize, G_SMEM);
    cudaFuncSetAttribute(flash_attn_f16, cudaFuncAttributeMaxDynamicSharedMemorySize, F_SMEM);

    __half *xh, *xl, *wh, *wl;
    cudaGetSymbolAddress((void**)&xh, g_x16h);
    cudaGetSymbolAddress((void**)&xl, g_x16l);
    cudaGetSymbolAddress((void**)&wh, g_w16h);
    cudaGetSymbolAddress((void**)&wl, g_w16l);

    split_f16<<<(MROWS * DIMC / 4 + 255) / 256, 256>>>(x, xh, xl, MROWS * DIMC / 4);
    split_f16<<<(DIMC * OUT3 / 4 + 255) / 256, 256>>>(w, wh, wl, DIMC * OUT3 / 4);

    dim3 g1(OUT3 / 256, MROWS / 128);   // (12, 64)
    qkv_gemm_f16<<<g1, 256, G_SMEM>>>();

    dim3 g2(BB * NHEADS, NN / 64);      // (64, 32)
    flash_attn_f16<<<g2, 128, F_SMEM>>>(out);
}